// round 2
// baseline (speedup 1.0000x reference)
#include <cuda_runtime.h>

#define NL 128   // rows of lines tables
#define CL 32    // embedding width
#define HD 128   // hidden dim

// Persistent device scratch (allocations are forbidden). All of these are
// left in a deterministic state (zeros / fully rewritten) at the end of every
// kernel_launch invocation, so graph replays are reproducible.
__device__ unsigned g_maskbits[12];   // [axis*4 + word]: 128-bit occupancy per axis
__device__ float    g_pre[8 * NL];    // [combo*128 + r]: precomputed head outputs
__device__ unsigned g_done;           // block completion counter

__global__ __launch_bounds__(256) void k_fused(
    const float4* __restrict__ c4, long long n128,
    const float*  __restrict__ cflat, long long nfloats,
    const float*  __restrict__ lines0, const float* __restrict__ lines1,
    const float*  __restrict__ lines2, const float* __restrict__ w1,
    const float*  __restrict__ b1, const float* __restrict__ w2,
    const float*  __restrict__ b2, float* __restrict__ out, long long nout)
{
    __shared__ float    s_red[8];
    __shared__ float    s_feats[CL];
    __shared__ float    s_c0;
    __shared__ unsigned s_m[8][12];
    __shared__ int      s_last;

    const int tid  = threadIdx.x;
    const int lane = tid & 31;
    const int wid  = tid >> 5;

    // ------------------------------------------------------------------
    // Phase A (all blocks): c0 = sum_j w2_j * relu(b1_j) + b2
    // (tail constant for rows >= NL; tiny, L2-served)
    // ------------------------------------------------------------------
    {
        float v = 0.f;
        if (tid < HD) v = fmaxf(__ldg(&b1[tid]), 0.f) * __ldg(&w2[tid]);
        #pragma unroll
        for (int o = 16; o; o >>= 1) v += __shfl_down_sync(~0u, v, o);
        if (tid < HD && lane == 0) s_red[wid] = v;
        __syncthreads();
        if (tid == 0) s_c0 = s_red[0] + s_red[1] + s_red[2] + s_red[3] + __ldg(&b2[0]);
        __syncthreads();
    }

    // ------------------------------------------------------------------
    // Phase B (blocks 0..1023): precompute g_pre[combo][r] for all 8 flag
    // combos x 128 rows. Fully hidden under the DRAM-bound scan.
    // ------------------------------------------------------------------
    if (blockIdx.x < 8 * NL) {
        const int combo = blockIdx.x >> 7;
        const int r     = blockIdx.x & (NL - 1);
        if (tid < CL) {
            float x = __ldg(&lines0[r * CL + tid]) * (float)(combo & 1);
            float y = __ldg(&lines1[r * CL + tid]) * (float)((combo >> 1) & 1);
            float z = __ldg(&lines2[r * CL + tid]) * (float)((combo >> 2) & 1);
            float f1 = x + y + z;
            float f2 = (x * y + x * z + y * z) / 0.4f;
            float f3 = x * y * z / 0.16000000000000003f;
            s_feats[tid] = f1 + f2 + f3;
        }
        __syncthreads();
        float term = 0.f;
        if (tid < HD) {
            float acc = __ldg(&b1[tid]);
            const float4* w4 = (const float4*)(w1 + tid * CL);
            #pragma unroll
            for (int q = 0; q < CL / 4; q++) {
                float4 wv = __ldg(&w4[q]);
                acc = fmaf(wv.x, s_feats[q * 4 + 0], acc);
                acc = fmaf(wv.y, s_feats[q * 4 + 1], acc);
                acc = fmaf(wv.z, s_feats[q * 4 + 2], acc);
                acc = fmaf(wv.w, s_feats[q * 4 + 3], acc);
            }
            term = fmaxf(acc, 0.f) * __ldg(&w2[tid]);
        }
        #pragma unroll
        for (int o = 16; o; o >>= 1) term += __shfl_down_sync(~0u, term, o);
        __syncthreads();  // s_red reuse
        if (tid < HD && lane == 0) s_red[wid] = term;
        __syncthreads();
        if (tid == 0)
            g_pre[blockIdx.x] = s_red[0] + s_red[1] + s_red[2] + s_red[3] + __ldg(&b2[0]);
    }

    // ------------------------------------------------------------------
    // Phase C: scan coordinates -> per-thread register bitmasks.
    // Warp consumes 96 consecutive float4s; flat index f = 4*(w*96+lane+32s)+i,
    // axis(f) = (lane + 2s + i) % 3 = (p + j) % 3 with p = lane%3 and
    // compile-time j = (2s + i) % 3. Accumulate into relative group m[j].
    // k = round((v+2)*32) == __float2int_rn(fmaf(v,32,64)) bit-exactly.
    // ------------------------------------------------------------------
    unsigned m[3][4] = {{0u,0u,0u,0u},{0u,0u,0u,0u},{0u,0u,0u,0u}};
    const int p = lane % 3;

#define PROCJ(v, J) {                                   \
        float t_ = fmaf((v), 32.0f, 64.0f);             \
        int k_ = __float2int_rn(t_);                    \
        unsigned s_ = (unsigned)k_ >> 5;                \
        unsigned msk_ = 1u << (k_ & 31);                \
        if      (s_ == 0u) m[J][0] |= msk_;             \
        else if (s_ == 1u) m[J][1] |= msk_;             \
        else if (s_ == 2u) m[J][2] |= msk_;             \
        else if (s_ == 3u) m[J][3] |= msk_; }

    const long long nwarps  = (long long)gridDim.x * (blockDim.x >> 5);
    const long long wg      = (long long)blockIdx.x * (blockDim.x >> 5) + wid;
    const long long nchunks = n128 / 96;

    for (long long w = wg; w < nchunks; w += nwarps) {
        const long long base = w * 96 + lane;
        float4 f0 = c4[base];
        float4 f1 = c4[base + 32];
        float4 f2 = c4[base + 64];
        PROCJ(f0.x, 0) PROCJ(f0.y, 1) PROCJ(f0.z, 2) PROCJ(f0.w, 0)
        PROCJ(f1.x, 2) PROCJ(f1.y, 0) PROCJ(f1.z, 1) PROCJ(f1.w, 2)
        PROCJ(f2.x, 1) PROCJ(f2.y, 2) PROCJ(f2.z, 0) PROCJ(f2.w, 1)
    }
#undef PROCJ

    const long long gid = (long long)blockIdx.x * blockDim.x + tid;
    const long long gsz = (long long)gridDim.x * blockDim.x;

    // float4 tail (n128 % 96) — direct atomics, rarely/never executed.
    for (long long q = nchunks * 96 + gid; q < n128; q += gsz) {
        float4 f = c4[q];
        float vv[4] = {f.x, f.y, f.z, f.w};
        #pragma unroll
        for (int i = 0; i < 4; i++) {
            long long fi = (q << 2) + i;
            int d = (int)(fi % 3);
            int k_ = __float2int_rn(fmaf(vv[i], 32.0f, 64.0f));
            if ((unsigned)k_ < 128u)
                atomicOr(&g_maskbits[d * 4 + (k_ >> 5)], 1u << (k_ & 31));
        }
    }
    // scalar tail (nfloats % 4)
    for (long long q = (n128 << 2) + gid; q < nfloats; q += gsz) {
        int d = (int)(q % 3);
        int k_ = __float2int_rn(fmaf(cflat[q], 32.0f, 64.0f));
        if ((unsigned)k_ < 128u)
            atomicOr(&g_maskbits[d * 4 + (k_ >> 5)], 1u << (k_ & 31));
    }

    // ------------------------------------------------------------------
    // Phase D: merge masks. Permute relative->absolute axis per lane, then
    // warp REDUX.OR, then one atomicOr per (block, word).
    // ------------------------------------------------------------------
    {
        unsigned a0[4], a1[4], a2[4];
        #pragma unroll
        for (int wq = 0; wq < 4; wq++) {
            a0[wq] = (p == 0) ? m[0][wq] : ((p == 1) ? m[2][wq] : m[1][wq]);
            a1[wq] = (p == 0) ? m[1][wq] : ((p == 1) ? m[0][wq] : m[2][wq]);
            a2[wq] = (p == 0) ? m[2][wq] : ((p == 1) ? m[1][wq] : m[0][wq]);
        }
        unsigned red[12];
        #pragma unroll
        for (int wq = 0; wq < 4; wq++) {
            red[wq]     = __reduce_or_sync(~0u, a0[wq]);
            red[4 + wq] = __reduce_or_sync(~0u, a1[wq]);
            red[8 + wq] = __reduce_or_sync(~0u, a2[wq]);
        }
        if (lane == 0) {
            #pragma unroll
            for (int i = 0; i < 12; i++) s_m[wid][i] = red[i];
        }
        __syncthreads();
        if (tid < 12) {
            unsigned v = 0u;
            #pragma unroll
            for (int wr = 0; wr < 8; wr++) v |= s_m[wr][tid];
            if (v) atomicOr(&g_maskbits[tid], v);
        }
    }

    // ------------------------------------------------------------------
    // Phase E: fill out[NL .. nout) with c0 (vectorized, all blocks).
    // ------------------------------------------------------------------
    {
        const float c0 = s_c0;
        const float4 cv = make_float4(c0, c0, c0, c0);
        float4* out4 = (float4*)out;
        const long long n4 = nout >> 2;
        for (long long q = (NL / 4) + gid; q < n4; q += gsz) out4[q] = cv;
        for (long long q = (n4 << 2) + gid; q < nout; q += gsz)
            if (q >= NL) out[q] = c0;
    }

    // ------------------------------------------------------------------
    // Phase F: last block finalizes rows [0, NL) and resets scratch.
    // ------------------------------------------------------------------
    __threadfence();
    if (tid == 0) {
        unsigned t = atomicAdd(&g_done, 1u);
        s_last = (t == (unsigned)(gridDim.x - 1)) ? 1 : 0;
    }
    __syncthreads();
    if (s_last) {
        __threadfence();  // acquire: see all blocks' g_maskbits / g_pre writes
        if (tid < NL) {
            const int r = tid;
            // .cg loads: bypass L1, read L2 where atomics/stores landed.
            unsigned w0 = __ldcg((const unsigned*)&g_maskbits[(r >> 5)]);
            unsigned w1b = __ldcg((const unsigned*)&g_maskbits[4 + (r >> 5)]);
            unsigned w2b = __ldcg((const unsigned*)&g_maskbits[8 + (r >> 5)]);
            unsigned fx = (w0 >> (r & 31)) & 1u;
            unsigned fy = (w1b >> (r & 31)) & 1u;
            unsigned fz = (w2b >> (r & 31)) & 1u;
            unsigned combo = fx | (fy << 1) | (fz << 2);
            if (r < nout) out[r] = __ldcg(&g_pre[combo * NL + r]);
        }
        __syncthreads();
        if (tid < 12) g_maskbits[tid] = 0u;   // reset for next replay
        if (tid == 0) g_done = 0u;
    }
}

// ---------------------------------------------------------------------------
extern "C" void kernel_launch(void* const* d_in, const int* in_sizes, int n_in,
                              void* d_out, int out_size) {
    const float* coords = (const float*)d_in[0];
    const float* lines0 = (const float*)d_in[1];
    const float* lines1 = (const float*)d_in[2];
    const float* lines2 = (const float*)d_in[3];
    const float* w1     = (const float*)d_in[4];
    const float* b1     = (const float*)d_in[5];
    const float* w2     = (const float*)d_in[6];
    const float* b2     = (const float*)d_in[7];
    float* out = (float*)d_out;

    const long long nfloats = in_sizes[0];
    const long long n128 = nfloats >> 2;

    k_fused<<<1184, 256>>>((const float4*)coords, n128, coords, nfloats,
                           lines0, lines1, lines2, w1, b1, w2, b2,
                           out, (long long)out_size);
}

// round 3
// speedup vs baseline: 2.2075x; 2.2075x over previous
#include <cuda_runtime.h>

#define NL 128   // rows of lines tables
#define CL 32    // embedding width
#define HD 128   // hidden dim
#define NFLAG (3 * NL)

// Persistent device scratch (allocations are forbidden). Left zeroed /
// fully-rewritten at the end of every launch => deterministic graph replays.
__device__ unsigned g_flags[NFLAG];   // occupancy flags per (axis, row)
__device__ float    g_pre[8 * NL];    // [combo*128 + r] precomputed head outputs
__device__ unsigned g_done;           // block completion counter

__global__ __launch_bounds__(256) void k_fused(
    const float4* __restrict__ c4, long long n128,
    const float*  __restrict__ cflat, long long nfloats,
    const float*  __restrict__ lines0, const float* __restrict__ lines1,
    const float*  __restrict__ lines2, const float* __restrict__ w1,
    const float*  __restrict__ b1, const float* __restrict__ w2,
    const float*  __restrict__ b2, float* __restrict__ out, long long nout)
{
    __shared__ unsigned sflag[NFLAG];
    __shared__ float    s_red[8];
    __shared__ float    s_feats[CL];
    __shared__ float    s_c0;
    __shared__ int      s_last;

    const int tid  = threadIdx.x;
    const int lane = tid & 31;
    const int wid  = tid >> 5;

    for (int i = tid; i < NFLAG; i += blockDim.x) sflag[i] = 0u;

    // ------------------------------------------------------------------
    // Phase A (all blocks): c0 = sum_j w2_j * relu(b1_j) + b2
    // ------------------------------------------------------------------
    {
        float v = 0.f;
        if (tid < HD) v = fmaxf(__ldg(&b1[tid]), 0.f) * __ldg(&w2[tid]);
        #pragma unroll
        for (int o = 16; o; o >>= 1) v += __shfl_down_sync(~0u, v, o);
        if (tid < HD && lane == 0) s_red[wid] = v;
        __syncthreads();
        if (tid == 0) s_c0 = s_red[0] + s_red[1] + s_red[2] + s_red[3] + __ldg(&b2[0]);
        __syncthreads();
    }

    // ------------------------------------------------------------------
    // Phase B (blocks 0..1023): precompute g_pre[combo][r], all 8 flag
    // combos x 128 rows. Hidden under the DRAM-bound scan.
    // (Condition is uniform per block, so the __syncthreads inside is safe.)
    // ------------------------------------------------------------------
    if (blockIdx.x < 8 * NL) {
        const int combo = blockIdx.x >> 7;
        const int r     = blockIdx.x & (NL - 1);
        if (tid < CL) {
            float x = __ldg(&lines0[r * CL + tid]) * (float)(combo & 1);
            float y = __ldg(&lines1[r * CL + tid]) * (float)((combo >> 1) & 1);
            float z = __ldg(&lines2[r * CL + tid]) * (float)((combo >> 2) & 1);
            float f1 = x + y + z;
            float f2 = (x * y + x * z + y * z) / 0.4f;
            float f3 = x * y * z / 0.16000000000000003f;
            s_feats[tid] = f1 + f2 + f3;
        }
        __syncthreads();
        float term = 0.f;
        if (tid < HD) {
            float acc = __ldg(&b1[tid]);
            const float4* w4 = (const float4*)(w1 + tid * CL);
            #pragma unroll
            for (int q = 0; q < CL / 4; q++) {
                float4 wv = __ldg(&w4[q]);
                acc = fmaf(wv.x, s_feats[q * 4 + 0], acc);
                acc = fmaf(wv.y, s_feats[q * 4 + 1], acc);
                acc = fmaf(wv.z, s_feats[q * 4 + 2], acc);
                acc = fmaf(wv.w, s_feats[q * 4 + 3], acc);
            }
            term = fmaxf(acc, 0.f) * __ldg(&w2[tid]);
        }
        #pragma unroll
        for (int o = 16; o; o >>= 1) term += __shfl_down_sync(~0u, term, o);
        __syncthreads();
        if (tid < HD && lane == 0) s_red[wid] = term;
        __syncthreads();
        if (tid == 0)
            g_pre[blockIdx.x] = s_red[0] + s_red[1] + s_red[2] + s_red[3] + __ldg(&b2[0]);
        __syncthreads();
    }

    // ------------------------------------------------------------------
    // Phase C: scan coordinates -> shared flags (predicated STS, 1-instr
    // body — NO divergent branch arms).
    // Warp consumes 96 consecutive float4s; flat idx f = 4*(w*96+lane+32s)+i,
    // axis(f) = (lane + 2s + i) % 3 = (p + j) % 3, p = lane%3, j compile-time.
    // k = round((v+2)*32) == __float2int_rn(fmaf(v,32,64)) bit-exactly.
    // Unroll x2 over chunks: 6 LDG.128 in flight before first consume.
    // ------------------------------------------------------------------
    const int p = lane % 3;
    int d1 = p + 1; if (d1 == 3) d1 = 0;
    int d2 = d1 + 1; if (d2 == 3) d2 = 0;
    const unsigned B0 = (unsigned)p  * NL;
    const unsigned B1 = (unsigned)d1 * NL;
    const unsigned B2 = (unsigned)d2 * NL;

#define PROC(v, BB) {                                                \
        float t_ = fmaf((v), 32.0f, 64.0f);                          \
        int k_ = __float2int_rn(t_);                                 \
        if ((unsigned)k_ < (unsigned)NL) sflag[(BB) + k_] = 1u; }

#define PROC_CHUNK(f0, f1, f2)                                       \
        PROC(f0.x, B0) PROC(f0.y, B1) PROC(f0.z, B2) PROC(f0.w, B0)  \
        PROC(f1.x, B2) PROC(f1.y, B0) PROC(f1.z, B1) PROC(f1.w, B2)  \
        PROC(f2.x, B1) PROC(f2.y, B2) PROC(f2.z, B0) PROC(f2.w, B1)

    const long long nwarps  = (long long)gridDim.x * (blockDim.x >> 5);
    const long long wg      = (long long)blockIdx.x * (blockDim.x >> 5) + wid;
    const long long nchunks = n128 / 96;

    long long w = wg;
    for (; w + nwarps < nchunks; w += 2 * nwarps) {
        const long long ba = w * 96 + lane;
        const long long bb = (w + nwarps) * 96 + lane;
        float4 a0 = c4[ba];
        float4 a1 = c4[ba + 32];
        float4 a2 = c4[ba + 64];
        float4 e0 = c4[bb];
        float4 e1 = c4[bb + 32];
        float4 e2 = c4[bb + 64];
        PROC_CHUNK(a0, a1, a2)
        PROC_CHUNK(e0, e1, e2)
    }
    if (w < nchunks) {
        const long long ba = w * 96 + lane;
        float4 a0 = c4[ba];
        float4 a1 = c4[ba + 32];
        float4 a2 = c4[ba + 64];
        PROC_CHUNK(a0, a1, a2)
    }

    const long long gid = (long long)blockIdx.x * blockDim.x + tid;
    const long long gsz = (long long)gridDim.x * blockDim.x;

    // float4 tail (n128 % 96) — runtime axis computation (usually empty).
    for (long long q = nchunks * 96 + gid; q < n128; q += gsz) {
        float4 f = c4[q];
        float vv[4] = {f.x, f.y, f.z, f.w};
        #pragma unroll
        for (int i = 0; i < 4; i++) {
            int d = (int)(((q << 2) + i) % 3);
            int k_ = __float2int_rn(fmaf(vv[i], 32.0f, 64.0f));
            if ((unsigned)k_ < (unsigned)NL) sflag[d * NL + k_] = 1u;
        }
    }
    // scalar tail (nfloats % 4) — safety only.
    for (long long q = (n128 << 2) + gid; q < nfloats; q += gsz) {
        int d = (int)(q % 3);
        int k_ = __float2int_rn(fmaf(cflat[q], 32.0f, 64.0f));
        if ((unsigned)k_ < (unsigned)NL) sflag[d * NL + k_] = 1u;
    }
#undef PROC_CHUNK
#undef PROC

    __syncthreads();
    for (int i = tid; i < NFLAG; i += blockDim.x)
        if (sflag[i]) g_flags[i] = 1u;   // benign race: all writers store 1

    // ------------------------------------------------------------------
    // Phase E: fill out[NL .. nout) with c0 (vectorized, all blocks).
    // ------------------------------------------------------------------
    {
        const float c0 = s_c0;
        const float4 cv = make_float4(c0, c0, c0, c0);
        float4* out4 = (float4*)out;
        const long long n4 = nout >> 2;
        for (long long q = (NL / 4) + gid; q < n4; q += gsz) out4[q] = cv;
        for (long long q = (n4 << 2) + gid; q < nout; q += gsz)
            if (q >= NL) out[q] = c0;
    }

    // ------------------------------------------------------------------
    // Phase F: last block finalizes rows [0, NL) and resets scratch.
    // ------------------------------------------------------------------
    __threadfence();
    if (tid == 0) {
        unsigned t = atomicAdd(&g_done, 1u);
        s_last = (t == (unsigned)(gridDim.x - 1)) ? 1 : 0;
    }
    __syncthreads();
    if (s_last) {
        __threadfence();  // acquire: see all blocks' g_flags / g_pre writes
        if (tid < NL) {
            const int r = tid;
            unsigned fx = __ldcg(&g_flags[r])          ? 1u : 0u;
            unsigned fy = __ldcg(&g_flags[NL + r])     ? 1u : 0u;
            unsigned fz = __ldcg(&g_flags[2 * NL + r]) ? 1u : 0u;
            unsigned combo = fx | (fy << 1) | (fz << 2);
            if (r < nout) out[r] = __ldcg(&g_pre[combo * NL + r]);
        }
        __syncthreads();
        for (int i = tid; i < NFLAG; i += blockDim.x) g_flags[i] = 0u;  // reset
        if (tid == 0) g_done = 0u;
    }
}

// ---------------------------------------------------------------------------
extern "C" void kernel_launch(void* const* d_in, const int* in_sizes, int n_in,
                              void* d_out, int out_size) {
    const float* coords = (const float*)d_in[0];
    const float* lines0 = (const float*)d_in[1];
    const float* lines1 = (const float*)d_in[2];
    const float* lines2 = (const float*)d_in[3];
    const float* w1     = (const float*)d_in[4];
    const float* b1     = (const float*)d_in[5];
    const float* w2     = (const float*)d_in[6];
    const float* b2     = (const float*)d_in[7];
    float* out = (float*)d_out;

    const long long nfloats = in_sizes[0];
    const long long n128 = nfloats >> 2;

    k_fused<<<1184, 256>>>((const float4*)coords, n128, coords, nfloats,
                           lines0, lines1, lines2, w1, b1, w2, b2,
                           out, (long long)out_size);
}